// round 9
// baseline (speedup 1.0000x reference)
#include <cuda_runtime.h>
#include <cuda_bf16.h>
#include <cstdint>

// LIF spiking scan:  x[B,S,H] -> spikes[B,S,H]   (B=8, S=2048, H=4096, fp32)
//   mem = decay*mem + x_t ; ref = max(ref-1,0)
//   spk = (ref==0 && mem>thr) ; mem *= (1-spk) ; ref += 5*spk
//
// Sequential over S, parallel over B*H = 32768 neurons. HBM-bound: 512 MB
// traffic, ~71 us floor. R6 (block-cooperative cp.async 6-stage pipeline) hit
// 100.4us @ 68.8% DRAM. Residual: the per-chunk __syncthreads couples all 4
// warps -> the block stalls on the slowest warp's wait_group (convoy effect).
// R7/R9: per-WARP independent pipelines. Each warp owns a 32-neuron column
// slice and copies exactly what it consumes; cp.async group accounting is
// per-thread, so wait_group + __syncwarp replaces the block barrier. Four
// free-running pipelines per block, zero cross-warp coupling.

#define LIF_B 8
#define LIF_S 2048
#define LIF_H 4096

static constexpr int U = 16;               // timesteps per stage
static constexpr int STAGES = 6;           // 6*16*128*4B = 48KB static smem (limit)
static constexpr int NCHUNK = LIF_S / U;   // 128
static constexpr float REFRACTORY = 5.0f;

__global__ __launch_bounds__(128, 1)
void lif_scan_warp_pipe(const float* __restrict__ x,
                        const float* __restrict__ thr_p,
                        const float* __restrict__ dec_p,
                        float* __restrict__ out)
{
    __shared__ float smem[STAGES][U][128];

    const int tid  = threadIdx.x;
    const int wid  = tid >> 5;               // warp 0..3, owns columns [32w,32w+32)
    const int lane = tid & 31;

    const int n0    = blockIdx.x * 128;      // first neuron of this block
    const int b     = n0 >> 12;              // n0 / H  (blocks never straddle b)
    const int hbase = n0 & (LIF_H - 1);      // n0 % H

    const float thr   = __ldg(thr_p);
    const float decay = __ldg(dec_p);

    const float* __restrict__ xbase = x   + b * (LIF_S * LIF_H) + hbase;
    float* __restrict__       obase = out + b * (LIF_S * LIF_H) + hbase + tid;

    // Per-warp copy role: warp's tile slice = 16 rows x 32 floats (128B/row).
    // lane -> (rows (lane>>3)+4j for j=0..3, float4 column lane&7).
    const int lrow = lane >> 3;    // 0..3
    const int lf4  = lane & 7;     // 0..7
    const int colb = wid * 32 + lf4 * 4;     // element column of this lane's float4
    const float* __restrict__ wsrc = xbase + lrow * LIF_H + colb;  // lane gmem base

    // Per-lane smem base for its float4 slot in row lrow of a stage.
    // Row stride inside a stage = 128 floats = 512B; stage stride = U*512B.
    const unsigned smem0 =
        (unsigned)__cvta_generic_to_shared(&smem[0][lrow][colb]);

    auto issue_chunk = [&](int c) {
        const unsigned sbase = smem0 + (unsigned)(c % STAGES) * (U * 512u);
        const float* src = wsrc + (c * U) * LIF_H;
        #pragma unroll
        for (int j = 0; j < 4; ++j) {
            asm volatile("cp.async.cg.shared.global [%0], [%1], 16;\n"
                         :: "r"(sbase + j * 4u * 512u),
                            "l"(src + j * 4 * LIF_H));
        }
    };

    // Prologue: fill STAGES-2 stages, one group each (per-thread accounting).
    #pragma unroll
    for (int c = 0; c < STAGES - 2; ++c) {
        issue_chunk(c);
        asm volatile("cp.async.commit_group;\n" ::: "memory");
    }

    float mem = 0.0f;
    float ref = 0.0f;

    for (int c = 0; c < NCHUNK; ++c) {
        if (c + STAGES - 2 < NCHUNK)
            issue_chunk(c + STAGES - 2);
        // Always commit (empty tail groups keep wait_group<STAGES-2> aligned
        // so chunk c's group is guaranteed complete below).
        asm volatile("cp.async.commit_group;\n" ::: "memory");
        asm volatile("cp.async.wait_group %0;\n" :: "n"(STAGES - 2) : "memory");
        __syncwarp();   // producer lanes == consumer lanes within this warp only

        const int s = c % STAGES;

        // Batch the 16 LDS (lanes hit consecutive banks; same-warp data).
        float v[U];
        #pragma unroll
        for (int i = 0; i < U; ++i)
            v[i] = smem[s][i][tid];

        float* __restrict__ o = obase + (c * U) * LIF_H;
        #pragma unroll
        for (int i = 0; i < U; ++i) {
            mem = fmaf(decay, mem, v[i]);
            ref = fmaxf(ref - 1.0f, 0.0f);
            const bool sp = (ref == 0.0f) && (mem > thr);
            const float spk = sp ? 1.0f : 0.0f;
            mem = sp ? 0.0f : mem;
            ref = fmaf(spk, REFRACTORY, ref);
            o[i * LIF_H] = spk;
        }
    }
}

extern "C" void kernel_launch(void* const* d_in, const int* in_sizes, int n_in,
                              void* d_out, int out_size)
{
    // metadata order: x [B,S,H] f32, membrane_threshold f32, decay_rate f32
    const float* x     = (const float*)d_in[0];
    const float* thr_p = (const float*)d_in[1];
    const float* dec_p = (const float*)d_in[2];
    float* out = (float*)d_out;

    const int blocks = (LIF_B * LIF_H) / 128;   // 256 blocks, exact cover

    lif_scan_warp_pipe<<<blocks, 128>>>(x, thr_p, dec_p, out);
}

// round 11
// speedup vs baseline: 1.0169x; 1.0169x over previous
#include <cuda_runtime.h>
#include <cuda_bf16.h>
#include <cstdint>

// LIF spiking scan:  x[B,S,H] -> spikes[B,S,H]   (B=8, S=2048, H=4096, fp32)
//   mem = decay*mem + x_t ; ref = max(ref-1,0)
//   spk = (ref==0 && mem>thr) ; mem *= (1-spk) ; ref += 5*spk
//
// R6 (block pipeline, 128-neuron blocks) = 100.4us @ 68.8% DRAM. R9 showed
// the block barrier was NOT the limiter (per-warp pipelines neutral). The
// real residual: 256 identical-work blocks over 148 SMs -> 108 SMs carry 2
// blocks, 40 carry 1 (max 256 neurons/SM vs avg 221) = 15.6% tail waste
// while DRAM sits unsaturated. R10/R11: 32-neuron single-warp blocks,
// grid=1024 -> 136 SMs x7 / 12 x6 (max 224 neurons/SM). Warp-private
// cp.async pipeline (8 stages, 16KB/block; 7 blocks = 112KB/SM resident),
// syncwarp only, no block barrier.

#define LIF_B 8
#define LIF_S 2048
#define LIF_H 4096

static constexpr int U = 16;               // timesteps per stage
static constexpr int STAGES = 8;           // 8*16*32*4B = 16KB smem/block
static constexpr int NCHUNK = LIF_S / U;   // 128
static constexpr float REFRACTORY = 5.0f;

__global__ __launch_bounds__(32, 7)
void lif_scan_warp32(const float* __restrict__ x,
                     const float* __restrict__ thr_p,
                     const float* __restrict__ dec_p,
                     float* __restrict__ out)
{
    __shared__ float smem[STAGES][U][32];

    const int lane = threadIdx.x;            // 0..31
    const int n0   = blockIdx.x * 32;        // first neuron of this block
    const int b     = n0 >> 12;              // n0 / H  (blocks never straddle b)
    const int hbase = n0 & (LIF_H - 1);      // n0 % H

    const float thr   = __ldg(thr_p);
    const float decay = __ldg(dec_p);

    const float* __restrict__ xbase = x   + b * (LIF_S * LIF_H) + hbase;
    float* __restrict__       obase = out + b * (LIF_S * LIF_H) + hbase + lane;

    // Copy role: chunk tile = 16 rows x 32 floats (128B rows). Each lane
    // copies 4 rows ((lane>>3)+4j) at float4 column (lane&7) -> 4x 16B
    // cp.async per chunk, each warp-row a full 128B sector.
    const int lrow = lane >> 3;    // 0..3
    const int colb = (lane & 7) * 4;
    const float* __restrict__ wsrc = xbase + lrow * LIF_H + colb;

    const unsigned smem0 =
        (unsigned)__cvta_generic_to_shared(&smem[0][lrow][colb]);

    auto issue_chunk = [&](int c) {
        const unsigned sbase = smem0 + (unsigned)(c % STAGES) * (U * 128u);
        const float* src = wsrc + (c * U) * LIF_H;
        #pragma unroll
        for (int j = 0; j < 4; ++j) {
            asm volatile("cp.async.cg.shared.global [%0], [%1], 16;\n"
                         :: "r"(sbase + j * 4u * 128u),
                            "l"(src + j * 4 * LIF_H));
        }
    };

    // Prologue: fill STAGES-2 stages, one group each.
    #pragma unroll
    for (int c = 0; c < STAGES - 2; ++c) {
        issue_chunk(c);
        asm volatile("cp.async.commit_group;\n" ::: "memory");
    }

    float mem = 0.0f;
    float ref = 0.0f;

    for (int c = 0; c < NCHUNK; ++c) {
        if (c + STAGES - 2 < NCHUNK)
            issue_chunk(c + STAGES - 2);
        // Always commit (empty tail groups keep wait_group<STAGES-2> aligned
        // so chunk c's group is guaranteed complete below).
        asm volatile("cp.async.commit_group;\n" ::: "memory");
        asm volatile("cp.async.wait_group %0;\n" :: "n"(STAGES - 2) : "memory");
        __syncwarp();   // single-warp block: producer == consumer warp

        const int s = c % STAGES;

        // Batch the 16 LDS (32 lanes -> 32 consecutive banks, conflict-free).
        float v[U];
        #pragma unroll
        for (int i = 0; i < U; ++i)
            v[i] = smem[s][i][lane];

        float* __restrict__ o = obase + (c * U) * LIF_H;
        #pragma unroll
        for (int i = 0; i < U; ++i) {
            mem = fmaf(decay, mem, v[i]);
            ref = fmaxf(ref - 1.0f, 0.0f);
            const bool sp = (ref == 0.0f) && (mem > thr);
            const float spk = sp ? 1.0f : 0.0f;
            mem = sp ? 0.0f : mem;
            ref = fmaf(spk, REFRACTORY, ref);
            o[i * LIF_H] = spk;
        }
    }
}

extern "C" void kernel_launch(void* const* d_in, const int* in_sizes, int n_in,
                              void* d_out, int out_size)
{
    // metadata order: x [B,S,H] f32, membrane_threshold f32, decay_rate f32
    const float* x     = (const float*)d_in[0];
    const float* thr_p = (const float*)d_in[1];
    const float* dec_p = (const float*)d_in[2];
    float* out = (float*)d_out;

    const int blocks = (LIF_B * LIF_H) / 32;   // 1024 blocks, exact cover

    lif_scan_warp32<<<blocks, 32>>>(x, thr_p, dec_p, out);
}

// round 12
// speedup vs baseline: 1.0772x; 1.0593x over previous
#include <cuda_runtime.h>
#include <cuda_bf16.h>
#include <cstdint>

// LIF spiking scan:  x[B,S,H] -> spikes[B,S,H]   (B=8, S=2048, H=4096, fp32)
//   mem = decay*mem + x_t ; ref = max(ref-1,0)
//   spk = (ref==0 && mem>thr) ; mem *= (1-spk) ; ref += 5*spk
//
// R6/R9/R11 all converge at ~86us ncu / ~5.6TB/s with DRAM only ~68% busy ->
// the limiter is the per-SM LSU issue queue, dominated by 16x STG.32 per
// chunk-warp (80 of ~144 LSU cycles). R12: 4 neurons per thread (float4
// lanes). LDS.128 + STG.128 cut LSU cost/unit 0.28 -> 0.1875 cyc and give 4
// independent FMA chains per thread. 8192 threads, 256 single-warp blocks,
// 6-stage cp.async pipeline (8KB/stage tile = 16 t x 512B contiguous rows,
// one 512B row per warp cp.async op).

#define LIF_B 8
#define LIF_S 2048
#define LIF_H 4096

static constexpr int U = 16;               // timesteps per stage
static constexpr int STAGES = 6;           // 6 * 16*128*4B = 48KB smem/block
static constexpr int NCHUNK = LIF_S / U;   // 128
static constexpr float REFRACTORY = 5.0f;

__global__ __launch_bounds__(32, 2)
void lif_scan_v4(const float* __restrict__ x,
                 const float* __restrict__ thr_p,
                 const float* __restrict__ dec_p,
                 float* __restrict__ out)
{
    __shared__ float smem[STAGES][U][128];   // per-stage tile: 16 t x 128 neurons

    const int lane = threadIdx.x;            // 0..31
    const int n0   = blockIdx.x * 128;       // first neuron of this block
    const int b     = n0 >> 12;              // n0 / H  (4096/128=32 blocks per b, exact)
    const int hbase = n0 & (LIF_H - 1);      // n0 % H

    const float thr   = __ldg(thr_p);
    const float decay = __ldg(dec_p);

    const float* __restrict__ xbase = x   + b * (LIF_S * LIF_H) + hbase;
    float* __restrict__       obase = out + b * (LIF_S * LIF_H) + hbase + lane * 4;

    // Copy role: tile row = 128 floats = 512B = one warp-wide cp.async op
    // (lane -> 16B at column lane*4). 16 ops per chunk, one per row.
    const float* __restrict__ wsrc = xbase + lane * 4;
    const unsigned smem0 =
        (unsigned)__cvta_generic_to_shared(&smem[0][0][lane * 4]);

    auto issue_chunk = [&](int c) {
        const unsigned sbase = smem0 + (unsigned)(c % STAGES) * (U * 512u);
        const float* src = wsrc + (c * U) * LIF_H;
        #pragma unroll
        for (int j = 0; j < U; ++j) {
            asm volatile("cp.async.cg.shared.global [%0], [%1], 16;\n"
                         :: "r"(sbase + (unsigned)j * 512u),
                            "l"(src + j * LIF_H));
        }
    };

    // Prologue: fill STAGES-2 stages, one commit group each.
    #pragma unroll
    for (int c = 0; c < STAGES - 2; ++c) {
        issue_chunk(c);
        asm volatile("cp.async.commit_group;\n" ::: "memory");
    }

    // 4 independent neuron states per thread (h, h+1, h+2, h+3).
    float mem0 = 0.f, mem1 = 0.f, mem2 = 0.f, mem3 = 0.f;
    float ref0 = 0.f, ref1 = 0.f, ref2 = 0.f, ref3 = 0.f;

    for (int c = 0; c < NCHUNK; ++c) {
        if (c + STAGES - 2 < NCHUNK)
            issue_chunk(c + STAGES - 2);
        // Always commit (empty tail groups keep wait_group<STAGES-2> aligned
        // so chunk c's group is guaranteed complete below).
        asm volatile("cp.async.commit_group;\n" ::: "memory");
        asm volatile("cp.async.wait_group %0;\n" :: "n"(STAGES - 2) : "memory");
        __syncwarp();   // single-warp block: producer == consumer warp

        const int s = c % STAGES;

        // Batch 16 LDS.128 (quarter-warp phases hit distinct banks).
        float4 v[U];
        #pragma unroll
        for (int i = 0; i < U; ++i)
            v[i] = *reinterpret_cast<const float4*>(&smem[s][i][lane * 4]);

        float* __restrict__ o = obase + (c * U) * LIF_H;
        #pragma unroll
        for (int i = 0; i < U; ++i) {
            float4 spk;

            mem0 = fmaf(decay, mem0, v[i].x);
            ref0 = fmaxf(ref0 - 1.0f, 0.0f);
            {
                const bool sp = (ref0 == 0.0f) && (mem0 > thr);
                spk.x = sp ? 1.0f : 0.0f;
                mem0 = sp ? 0.0f : mem0;
                ref0 = fmaf(spk.x, REFRACTORY, ref0);
            }
            mem1 = fmaf(decay, mem1, v[i].y);
            ref1 = fmaxf(ref1 - 1.0f, 0.0f);
            {
                const bool sp = (ref1 == 0.0f) && (mem1 > thr);
                spk.y = sp ? 1.0f : 0.0f;
                mem1 = sp ? 0.0f : mem1;
                ref1 = fmaf(spk.y, REFRACTORY, ref1);
            }
            mem2 = fmaf(decay, mem2, v[i].z);
            ref2 = fmaxf(ref2 - 1.0f, 0.0f);
            {
                const bool sp = (ref2 == 0.0f) && (mem2 > thr);
                spk.z = sp ? 1.0f : 0.0f;
                mem2 = sp ? 0.0f : mem2;
                ref2 = fmaf(spk.z, REFRACTORY, ref2);
            }
            mem3 = fmaf(decay, mem3, v[i].w);
            ref3 = fmaxf(ref3 - 1.0f, 0.0f);
            {
                const bool sp = (ref3 == 0.0f) && (mem3 > thr);
                spk.w = sp ? 1.0f : 0.0f;
                mem3 = sp ? 0.0f : mem3;
                ref3 = fmaf(spk.w, REFRACTORY, ref3);
            }

            *reinterpret_cast<float4*>(&o[i * LIF_H]) = spk;   // STG.128
        }
    }
}

extern "C" void kernel_launch(void* const* d_in, const int* in_sizes, int n_in,
                              void* d_out, int out_size)
{
    // metadata order: x [B,S,H] f32, membrane_threshold f32, decay_rate f32
    const float* x     = (const float*)d_in[0];
    const float* thr_p = (const float*)d_in[1];
    const float* dec_p = (const float*)d_in[2];
    float* out = (float*)d_out;

    const int blocks = (LIF_B * LIF_H) / 128;   // 256 blocks, exact cover

    lif_scan_v4<<<blocks, 32>>>(x, thr_p, dec_p, out);
}